// round 6
// baseline (speedup 1.0000x reference)
#include <cuda_runtime.h>
#include <math.h>

#define BB   512
#define PP   256
#define MAXW 0.1f
#define EPSI 1e-8f
#define NPGD 250
#define NPOW 20
#define NRND 8                        // 16-way rounds: 17^8 ≈ 2^32.7 > reference 2^30

#define RP        260                 // padded row length in floats (260 ≡ 4 mod 32 → conflict-free)
#define SROWS     128                 // rows of sigma kept in SMEM (rows 0..127)
#define SIG_WORDS (SROWS * RP)        // 33280
#define XS_OFF    SIG_WORDS           // current vector (w or power-iter v), 256 floats
#define VS_OFF    (SIG_WORDS + 256)   // staging vector, 256 floats
#define FL_OFF    (SIG_WORDS + 512)   // 32 int flags (double-buffered 16+16)
#define SMEM_WORDS (SIG_WORDS + 544)
#define SMEM_BYTES (SMEM_WORDS * 4)   // 135296 B

// 32-lane butterfly sum (used only in rare spots: power iteration + epilogue)
__device__ __forceinline__ float bfly_add(float v) {
#pragma unroll
    for (int o = 16; o >= 1; o >>= 1) v += __shfl_xor_sync(0xffffffffu, v, o);
    return v;
}

// Mat-vec: y = sigma * x for this batch. Rows 0..127 from SMEM, rows 128..255 from
// register-resident rf[64] (this thread owns row_hi, cols col0..col0+63 in staggered order).
// Thread t: row_lo = t>>2, row_hi = 128 + (t>>2), chunk = t&3, col0 = 64*chunk.
__device__ __forceinline__ void matvec256(const float* __restrict__ sm,
                                          const float (&rf)[64],
                                          int sbase, int xbase, int chunk,
                                          float& Y0, float& Y1) {
    float a0 = 0.f, b0 = 0.f, a1 = 0.f, b1 = 0.f;
#pragma unroll
    for (int i = 0; i < 16; i++) {
        const int cm = 4 * ((i + 2 * chunk) & 15);
        const float4 xv = *reinterpret_cast<const float4*>(&sm[xbase + cm]);
        const float4 sv = *reinterpret_cast<const float4*>(&sm[sbase + cm]);
        if (i & 1) {
            b0 = fmaf(sv.x, xv.x, b0); b0 = fmaf(sv.y, xv.y, b0);
            b0 = fmaf(sv.z, xv.z, b0); b0 = fmaf(sv.w, xv.w, b0);
            b1 = fmaf(rf[4 * i + 0], xv.x, b1); b1 = fmaf(rf[4 * i + 1], xv.y, b1);
            b1 = fmaf(rf[4 * i + 2], xv.z, b1); b1 = fmaf(rf[4 * i + 3], xv.w, b1);
        } else {
            a0 = fmaf(sv.x, xv.x, a0); a0 = fmaf(sv.y, xv.y, a0);
            a0 = fmaf(sv.z, xv.z, a0); a0 = fmaf(sv.w, xv.w, a0);
            a1 = fmaf(rf[4 * i + 0], xv.x, a1); a1 = fmaf(rf[4 * i + 1], xv.y, a1);
            a1 = fmaf(rf[4 * i + 2], xv.z, a1); a1 = fmaf(rf[4 * i + 3], xv.w, a1);
        }
    }
    a0 += b0; a1 += b1;
    // combine the 4 column-chunks (lanes differing in low 2 bits) — all 4 get full sum
    a0 += __shfl_xor_sync(0xffffffffu, a0, 1);
    a1 += __shfl_xor_sync(0xffffffffu, a1, 1);
    a0 += __shfl_xor_sync(0xffffffffu, a0, 2);
    a1 += __shfl_xor_sync(0xffffffffu, a1, 2);
    Y0 = a0; Y1 = a1;
}

__global__ __launch_bounds__(512, 1)
void drb_kernel(const float* __restrict__ sigma,
                const float* __restrict__ beta,
                const float* __restrict__ wprev,
                const float* __restrict__ ll1,
                const float* __restrict__ ll2,
                float* __restrict__ out) {
    extern __shared__ float sm[];
    int* const smi = reinterpret_cast<int*>(sm);
    const int tid    = threadIdx.x;
    const int b      = blockIdx.x;
    const int chunk  = tid & 3;
    const int col0   = chunk * 64;
    const int row_lo = tid >> 2;          // 0..127
    const int row_hi = 128 + row_lo;      // 128..255
    const int lane   = tid & 31;
    const int wid    = tid >> 5;          // 0..15
    const int sbase  = row_lo * RP + col0;
    const int xbase  = XS_OFF + col0;

    const float lam1 = expf(ll1[0]);
    const float lam2 = expf(ll2[0]);

    const size_t gb = (size_t)b * PP * PP;

    // ---- load register-resident half of sigma (rows 128..255), staggered col order ----
    float rf[64];
    {
        const float* grow = sigma + gb + (size_t)row_hi * PP + col0;
#pragma unroll
        for (int i = 0; i < 16; i++) {
            const int cm = 4 * ((i + 2 * chunk) & 15);
            const float4 v = *reinterpret_cast<const float4*>(&grow[cm]);
            rf[4 * i + 0] = v.x; rf[4 * i + 1] = v.y;
            rf[4 * i + 2] = v.z; rf[4 * i + 3] = v.w;
        }
    }

    // ---- load SMEM-resident half of sigma (rows 0..127), padded rows ----
    for (int idx = tid; idx < SROWS * 64; idx += 512) {
        const int r = idx >> 6, c4 = idx & 63;
        const float4 v = *reinterpret_cast<const float4*>(&sigma[gb + (size_t)r * PP + c4 * 4]);
        *reinterpret_cast<float4*>(&sm[r * RP + c4 * 4]) = v;
    }

    // per-row constants for the gradient (only chunk==0 threads use them)
    const float beta0 = beta[b * PP + row_lo];
    const float beta1 = beta[b * PP + row_hi];
    const float wp0   = wprev[b * PP + row_lo];
    const float wp1   = wprev[b * PP + row_hi];

    // ---- power iteration: v0 = 1/sqrt(P) ----
    if (tid < 256) sm[XS_OFF + tid] = 0.0625f;
    __syncthreads();

    for (int it = 0; it < NPOW; it++) {
        float u0, u1;
        matvec256(sm, rf, sbase, xbase, chunk, u0, u1);
        if (chunk == 0) { sm[VS_OFF + row_lo] = u0; sm[VS_OFF + row_hi] = u1; }
        __syncthreads();
        float ns = 0.f;
#pragma unroll
        for (int k = 0; k < 8; k++) {
            const float t = sm[VS_OFF + lane + 32 * k];
            ns = fmaf(t, t, ns);
        }
        ns = bfly_add(ns);
        const float inv = 1.0f / (sqrtf(ns) + EPSI);
        if (tid < 256) sm[XS_OFF + tid] = sm[VS_OFF + tid] * inv;
        __syncthreads();
    }

    // ---- lmax = v' S v, step = 1/(2 lmax + 2 lam2 + 1e-6) ----
    float step;
    {
        float u0, u1;
        matvec256(sm, rf, sbase, xbase, chunk, u0, u1);
        if (chunk == 0) {
            sm[VS_OFF + row_lo] = u0 * sm[XS_OFF + row_lo];
            sm[VS_OFF + row_hi] = u1 * sm[XS_OFF + row_hi];
        }
        __syncthreads();
        float lm = 0.f;
#pragma unroll
        for (int k = 0; k < 8; k++) lm += sm[VS_OFF + lane + 32 * k];
        lm = bfly_add(lm);
        step = 1.0f / (2.0f * lm + 2.0f * lam2 + 1e-6f);
        if (tid < 256) sm[XS_OFF + tid] = 1.0f / 256.0f;   // w0 = 1/P
        __syncthreads();
    }

    // ---- projected gradient descent ----
    for (int it = 0; it < NPGD; it++) {
        float y0, y1;
        matvec256(sm, rf, sbase, xbase, chunk, y0, y1);
        if (chunk == 0) {
            const float w0 = sm[XS_OFF + row_lo];
            const float w1 = sm[XS_OFF + row_hi];
            const float g0 = fmaf(2.0f, y0, -beta0) + lam1 + 2.0f * lam2 * (w0 - wp0);
            const float g1 = fmaf(2.0f, y1, -beta1) + lam1 + 2.0f * lam2 * (w1 - wp1);
            sm[VS_OFF + row_lo] = fmaf(-step, g0, w0);
            sm[VS_OFF + row_hi] = fmaf(-step, g1, w1);
        }
        __syncthreads();

        // ---- projection onto {sum w = 1, 0 <= w <= MAXW} ----
        // All 16 warps hold the full 256-vector replicated (8 vals/lane). Each round,
        // warp w evaluates its own candidate tau_w = lo + (w+1)*d, d = (hi-lo)/17.
        // Warp sums via fixed-point REDUX.SUM (values in [0,0.1] -> scale 2^25).
        // The 16 boolean flags select the surviving sub-interval: 17x shrink/round.
        float vr[8];
#pragma unroll
        for (int k = 0; k < 8; k++) vr[k] = sm[VS_OFF + lane + 32 * k];

        float mn = vr[0], mx = vr[0];
#pragma unroll
        for (int k = 1; k < 8; k++) { mn = fminf(mn, vr[k]); mx = fmaxf(mx, vr[k]); }
#pragma unroll
        for (int o = 16; o >= 1; o >>= 1) {
            mn = fminf(mn, __shfl_xor_sync(0xffffffffu, mn, o));
            mx = fmaxf(mx, __shfl_xor_sync(0xffffffffu, mx, o));
        }
        float lo = mn - MAXW, hi = mx;

        for (int r = 0; r < NRND; r++) {
            const float d   = (hi - lo) * (1.0f / 17.0f);
            const float tau = fmaf((float)(wid + 1), d, lo);
            float s = 0.f;
#pragma unroll
            for (int k = 0; k < 8; k++)
                s += fminf(fmaxf(vr[k] - tau, 0.f), MAXW);
            int si = __float2int_rn(s * 33554432.0f);           // 2^25 fixed point
            si = __reduce_add_sync(0xffffffffu, si);            // REDUX.SUM, warp total
            const int buf = FL_OFF + ((r & 1) << 4);            // double-buffer flags
            if (lane == 0) smi[buf + wid] = (si > 33554432) ? 1 : 0;   // s > 1.0
            __syncthreads();
            const int f = (lane < 16) ? smi[buf + lane] : 0;
            const unsigned bm = __ballot_sync(0xffffffffu, f != 0);
            const int cnt = __popc(bm & 0xffffu);               // # taus with s > 1
            const float nlo = fmaf((float)cnt, d, lo);
            hi = fmaf((float)(cnt + 1), d, lo);
            lo = nlo;
        }
        const float tau = 0.5f * (lo + hi);

        if (wid == 0) {   // all warps hold identical lo/hi; one writes
#pragma unroll
            for (int k = 0; k < 8; k++)
                sm[XS_OFF + lane + 32 * k] = fminf(fmaxf(vr[k] - tau, 0.f), MAXW);
        }
        __syncthreads();
    }

    // ---- post: renormalize w / (sum + eps) ----
    float s = 0.f;
#pragma unroll
    for (int k = 0; k < 8; k++) s += sm[XS_OFF + lane + 32 * k];
    s = bfly_add(s);
    const float inv = 1.0f / (s + EPSI);
    if (tid < 256) out[(size_t)b * PP + tid] = sm[XS_OFF + tid] * inv;
}

extern "C" void kernel_launch(void* const* d_in, const int* in_sizes, int n_in,
                              void* d_out, int out_size) {
    const float* sigma = (const float*)d_in[0];
    const float* beta  = (const float*)d_in[1];
    const float* wprev = (const float*)d_in[2];
    const float* ll1   = (const float*)d_in[3];
    const float* ll2   = (const float*)d_in[4];
    float* out = (float*)d_out;

    cudaFuncSetAttribute(drb_kernel, cudaFuncAttributeMaxDynamicSharedMemorySize, SMEM_BYTES);
    drb_kernel<<<BB, 512, SMEM_BYTES>>>(sigma, beta, wprev, ll1, ll2, out);
}

// round 7
// speedup vs baseline: 1.3906x; 1.3906x over previous
#include <cuda_runtime.h>
#include <math.h>

#define BB   512
#define PP   256
#define MAXW 0.1f
#define EPSI 1e-8f
#define NPGD 250
#define NPOW 20

#define RP        260                 // padded row length in floats (260 ≡ 4 mod 32 → conflict-free)
#define SROWS     128                 // rows of sigma kept in SMEM (rows 0..127)
#define SIG_WORDS (SROWS * RP)        // 33280
#define XS_OFF    SIG_WORDS           // current vector (w or power-iter v), 256 floats
#define VS_OFF    (SIG_WORDS + 256)   // staging vector, 256 floats
#define FL_OFF    (SIG_WORDS + 512)   // 32 int flags (double-buffered 16+16)
#define SMEM_WORDS (SIG_WORDS + 544)
#define SMEM_BYTES (SMEM_WORDS * 4)   // 135296 B

#define FPSCALE 33554432.0f           // 2^25 fixed point for clamped sums (max 25.6 -> fits s32)
#define FPONE   33554432

// 32-lane butterfly sum (cold paths only: power iteration + epilogue)
__device__ __forceinline__ float bfly_add(float v) {
#pragma unroll
    for (int o = 16; o >= 1; o >>= 1) v += __shfl_xor_sync(0xffffffffu, v, o);
    return v;
}

// monotone float <-> u32 key (order-preserving), for REDUX-based min/max
__device__ __forceinline__ unsigned fkey(float f) {
    int i = __float_as_int(f);
    unsigned u = (unsigned)i;
    return (i >= 0) ? (u | 0x80000000u) : ~u;
}
__device__ __forceinline__ float funkey(unsigned u) {
    return __int_as_float((u & 0x80000000u) ? (int)(u ^ 0x80000000u) : (int)(~u));
}

// Mat-vec: y = sigma * x. Rows 0..127 from SMEM, rows 128..255 from register file rf[64].
// Thread t: row_lo = t>>2, row_hi = 128 + (t>>2), chunk = t&3, cols staggered per chunk.
__device__ __forceinline__ void matvec256(const float* __restrict__ sm,
                                          const float (&rf)[64],
                                          int sbase, int xbase, int chunk,
                                          float& Y0, float& Y1) {
    float a0 = 0.f, b0 = 0.f, a1 = 0.f, b1 = 0.f;
#pragma unroll
    for (int i = 0; i < 16; i++) {
        const int cm = 4 * ((i + 2 * chunk) & 15);
        const float4 xv = *reinterpret_cast<const float4*>(&sm[xbase + cm]);
        const float4 sv = *reinterpret_cast<const float4*>(&sm[sbase + cm]);
        if (i & 1) {
            b0 = fmaf(sv.x, xv.x, b0); b0 = fmaf(sv.y, xv.y, b0);
            b0 = fmaf(sv.z, xv.z, b0); b0 = fmaf(sv.w, xv.w, b0);
            b1 = fmaf(rf[4 * i + 0], xv.x, b1); b1 = fmaf(rf[4 * i + 1], xv.y, b1);
            b1 = fmaf(rf[4 * i + 2], xv.z, b1); b1 = fmaf(rf[4 * i + 3], xv.w, b1);
        } else {
            a0 = fmaf(sv.x, xv.x, a0); a0 = fmaf(sv.y, xv.y, a0);
            a0 = fmaf(sv.z, xv.z, a0); a0 = fmaf(sv.w, xv.w, a0);
            a1 = fmaf(rf[4 * i + 0], xv.x, a1); a1 = fmaf(rf[4 * i + 1], xv.y, a1);
            a1 = fmaf(rf[4 * i + 2], xv.z, a1); a1 = fmaf(rf[4 * i + 3], xv.w, a1);
        }
    }
    a0 += b0; a1 += b1;
    a0 += __shfl_xor_sync(0xffffffffu, a0, 1);
    a1 += __shfl_xor_sync(0xffffffffu, a1, 1);
    a0 += __shfl_xor_sync(0xffffffffu, a0, 2);
    a1 += __shfl_xor_sync(0xffffffffu, a1, 2);
    Y0 = a0; Y1 = a1;
}

__global__ __launch_bounds__(512, 1)
void drb_kernel(const float* __restrict__ sigma,
                const float* __restrict__ beta,
                const float* __restrict__ wprev,
                const float* __restrict__ ll1,
                const float* __restrict__ ll2,
                float* __restrict__ out) {
    extern __shared__ float sm[];
    int* const smi = reinterpret_cast<int*>(sm);
    const int tid    = threadIdx.x;
    const int b      = blockIdx.x;
    const int chunk  = tid & 3;
    const int col0   = chunk * 64;
    const int row_lo = tid >> 2;          // 0..127
    const int row_hi = 128 + row_lo;      // 128..255
    const int lane   = tid & 31;
    const int wid    = tid >> 5;          // 0..15
    const int sbase  = row_lo * RP + col0;
    const int xbase  = XS_OFF + col0;

    const float lam1 = expf(ll1[0]);
    const float lam2 = expf(ll2[0]);

    const size_t gb = (size_t)b * PP * PP;

    // ---- register-resident half of sigma (rows 128..255), staggered col order ----
    float rf[64];
    {
        const float* grow = sigma + gb + (size_t)row_hi * PP + col0;
#pragma unroll
        for (int i = 0; i < 16; i++) {
            const int cm = 4 * ((i + 2 * chunk) & 15);
            const float4 v = *reinterpret_cast<const float4*>(&grow[cm]);
            rf[4 * i + 0] = v.x; rf[4 * i + 1] = v.y;
            rf[4 * i + 2] = v.z; rf[4 * i + 3] = v.w;
        }
    }

    // ---- SMEM-resident half of sigma (rows 0..127), padded rows ----
    for (int idx = tid; idx < SROWS * 64; idx += 512) {
        const int r = idx >> 6, c4 = idx & 63;
        const float4 v = *reinterpret_cast<const float4*>(&sigma[gb + (size_t)r * PP + c4 * 4]);
        *reinterpret_cast<float4*>(&sm[r * RP + c4 * 4]) = v;
    }

    const float beta0 = beta[b * PP + row_lo];
    const float beta1 = beta[b * PP + row_hi];
    const float wp0   = wprev[b * PP + row_lo];
    const float wp1   = wprev[b * PP + row_hi];

    // ---- power iteration: v0 = 1/sqrt(P) ----
    if (tid < 256) sm[XS_OFF + tid] = 0.0625f;
    __syncthreads();

    for (int it = 0; it < NPOW; it++) {
        float u0, u1;
        matvec256(sm, rf, sbase, xbase, chunk, u0, u1);
        if (chunk == 0) { sm[VS_OFF + row_lo] = u0; sm[VS_OFF + row_hi] = u1; }
        __syncthreads();
        float ns = 0.f;
#pragma unroll
        for (int k = 0; k < 8; k++) {
            const float t = sm[VS_OFF + lane + 32 * k];
            ns = fmaf(t, t, ns);
        }
        ns = bfly_add(ns);
        const float inv = 1.0f / (sqrtf(ns) + EPSI);
        if (tid < 256) sm[XS_OFF + tid] = sm[VS_OFF + tid] * inv;
        __syncthreads();
    }

    // ---- lmax = v' S v, step = 1/(2 lmax + 2 lam2 + 1e-6) ----
    float step;
    {
        float u0, u1;
        matvec256(sm, rf, sbase, xbase, chunk, u0, u1);
        if (chunk == 0) {
            sm[VS_OFF + row_lo] = u0 * sm[XS_OFF + row_lo];
            sm[VS_OFF + row_hi] = u1 * sm[XS_OFF + row_hi];
        }
        __syncthreads();
        float lm = 0.f;
#pragma unroll
        for (int k = 0; k < 8; k++) lm += sm[VS_OFF + lane + 32 * k];
        lm = bfly_add(lm);
        step = 1.0f / (2.0f * lm + 2.0f * lam2 + 1e-6f);
        if (tid < 256) sm[XS_OFF + tid] = 1.0f / 256.0f;   // w0 = 1/P
        __syncthreads();
    }

    // warm-start state for the projection (uniform across the whole block)
    float tau_p = 0.f, dtau = 0.f;
    int   have_warm = 0;
    int   parity = 0;
    const int kk  = wid >> 1;            // which vr reg this warp writes back
    const int wsel = ((lane >> 4) == (wid & 1));

    // ---- projected gradient descent ----
    for (int it = 0; it < NPGD; it++) {
        float y0, y1;
        matvec256(sm, rf, sbase, xbase, chunk, y0, y1);
        if (chunk == 0) {
            const float w0 = sm[XS_OFF + row_lo];
            const float w1 = sm[XS_OFF + row_hi];
            const float g0 = fmaf(2.0f, y0, -beta0) + lam1 + 2.0f * lam2 * (w0 - wp0);
            const float g1 = fmaf(2.0f, y1, -beta1) + lam1 + 2.0f * lam2 * (w1 - wp1);
            sm[VS_OFF + row_lo] = fmaf(-step, g0, w0);
            sm[VS_OFF + row_hi] = fmaf(-step, g1, w1);
        }
        __syncthreads();

        // ---- projection onto {sum w = 1, 0 <= w <= MAXW} ----
        // Full 256-vector replicated per warp (8 vals/lane). Each round evaluates 64
        // candidate taus (4 per warp, incl. both endpoints) with fixed-point REDUX sums:
        // 63x interval shrink per round. Warm-started bracket -> typically 1 round.
        float vr[8];
#pragma unroll
        for (int k = 0; k < 8; k++) vr[k] = sm[VS_OFF + lane + 32 * k];

        float lo, hi;
        if (have_warm) {
            const float delta = fmaf(4.0f, dtau, 1e-6f);
            lo = tau_p - delta; hi = tau_p + delta;
        } else {
            float mn = fminf(fminf(fminf(vr[0], vr[1]), fminf(vr[2], vr[3])),
                             fminf(fminf(vr[4], vr[5]), fminf(vr[6], vr[7])));
            float mx = fmaxf(fmaxf(fmaxf(vr[0], vr[1]), fmaxf(vr[2], vr[3])),
                             fmaxf(fmaxf(vr[4], vr[5]), fmaxf(vr[6], vr[7])));
            mn = funkey(__reduce_min_sync(0xffffffffu, fkey(mn)));
            mx = funkey(__reduce_max_sync(0xffffffffu, fkey(mx)));
            lo = mn - MAXW; hi = mx;
        }

        int rounds = 0;
        while (hi - lo > 4e-8f && rounds < 10) {
            rounds++;
            const float d    = (hi - lo) * (1.0f / 63.0f);
            const float base = fmaf((float)(4 * wid), d, lo);
            int local = 0;
#pragma unroll
            for (int j = 0; j < 4; j++) {
                const float tau = fmaf((float)j, d, base);
                float s0 = fminf(fmaxf(vr[0] - tau, 0.f), MAXW) + fminf(fmaxf(vr[1] - tau, 0.f), MAXW);
                float s1 = fminf(fmaxf(vr[2] - tau, 0.f), MAXW) + fminf(fmaxf(vr[3] - tau, 0.f), MAXW);
                float s2 = fminf(fmaxf(vr[4] - tau, 0.f), MAXW) + fminf(fmaxf(vr[5] - tau, 0.f), MAXW);
                float s3 = fminf(fmaxf(vr[6] - tau, 0.f), MAXW) + fminf(fmaxf(vr[7] - tau, 0.f), MAXW);
                const float s = (s0 + s1) + (s2 + s3);
                int si = __float2int_rn(s * FPSCALE);
                si = __reduce_add_sync(0xffffffffu, si);
                local += (si > FPONE);
            }
            const int buf = FL_OFF + ((parity & 1) << 4);
            parity ^= 1;
            if (lane == 0) smi[buf + wid] = local;
            __syncthreads();
            const int f = (lane < 16) ? smi[buf + lane] : 0;
            const int cnt = __reduce_add_sync(0xffffffffu, f);
            if (cnt == 0 || cnt == 64) {
                // warm bracket missed the root: rebuild the guaranteed-valid full bracket
                float mn = fminf(fminf(fminf(vr[0], vr[1]), fminf(vr[2], vr[3])),
                                 fminf(fminf(vr[4], vr[5]), fminf(vr[6], vr[7])));
                float mx = fmaxf(fmaxf(fmaxf(vr[0], vr[1]), fmaxf(vr[2], vr[3])),
                                 fmaxf(fmaxf(vr[4], vr[5]), fmaxf(vr[6], vr[7])));
                mn = funkey(__reduce_min_sync(0xffffffffu, fkey(mn)));
                mx = funkey(__reduce_max_sync(0xffffffffu, fkey(mx)));
                lo = mn - MAXW; hi = mx;
            } else {
                const float nlo = fmaf((float)(cnt - 1), d, lo);
                hi = fmaf((float)cnt, d, lo);
                lo = nlo;
            }
        }
        const float tau = 0.5f * (lo + hi);
        dtau = fabsf(tau - tau_p);
        tau_p = tau;
        have_warm = 1;

        // distributed write-back: warp w writes its 16 indices (one STS per half-warp)
        if (wsel) sm[XS_OFF + lane + 32 * kk] = fminf(fmaxf(vr[kk] - tau, 0.f), MAXW);
        __syncthreads();
    }

    // ---- post: renormalize w / (sum + eps) ----
    float s = 0.f;
#pragma unroll
    for (int k = 0; k < 8; k++) s += sm[XS_OFF + lane + 32 * k];
    s = bfly_add(s);
    const float inv = 1.0f / (s + EPSI);
    if (tid < 256) out[(size_t)b * PP + tid] = sm[XS_OFF + tid] * inv;
}

extern "C" void kernel_launch(void* const* d_in, const int* in_sizes, int n_in,
                              void* d_out, int out_size) {
    const float* sigma = (const float*)d_in[0];
    const float* beta  = (const float*)d_in[1];
    const float* wprev = (const float*)d_in[2];
    const float* ll1   = (const float*)d_in[3];
    const float* ll2   = (const float*)d_in[4];
    float* out = (float*)d_out;

    cudaFuncSetAttribute(drb_kernel, cudaFuncAttributeMaxDynamicSharedMemorySize, SMEM_BYTES);
    drb_kernel<<<BB, 512, SMEM_BYTES>>>(sigma, beta, wprev, ll1, ll2, out);
}

// round 9
// speedup vs baseline: 1.9965x; 1.4357x over previous
#include <cuda_runtime.h>
#include <math.h>

#define BB   512
#define PP   256
#define MAXW 0.1f
#define EPSI 1e-8f
#define NPGD 250
#define NPOW 20

#define RP        260                 // padded row length in floats (260 ≡ 4 mod 32 → conflict-free)
#define SROWS     128                 // rows of sigma kept in SMEM (rows 0..127)
#define SIG_WORDS (SROWS * RP)        // 33280
#define XS_OFF    SIG_WORDS           // current vector (w or power-iter v), 256 floats
#define VS_OFF    (SIG_WORDS + 256)   // staging vector, 256 floats
#define FL_OFF    (SIG_WORDS + 512)   // 2 ints: convergence flags (double-buffered)
#define SMEM_WORDS (SIG_WORDS + 544)
#define SMEM_BYTES (SMEM_WORDS * 4)   // 135296 B

#define FPSCALE 33554432.0f           // 2^25 fixed point for clamped sums (max 25.6 -> fits s32)
#define FPONE   33554432

// 32-lane butterfly sum (cold paths only: power iteration + epilogue)
__device__ __forceinline__ float bfly_add(float v) {
#pragma unroll
    for (int o = 16; o >= 1; o >>= 1) v += __shfl_xor_sync(0xffffffffu, v, o);
    return v;
}

// monotone float <-> u32 key (order-preserving), for REDUX-based min/max
__device__ __forceinline__ unsigned fkey(float f) {
    int i = __float_as_int(f);
    unsigned u = (unsigned)i;
    return (i >= 0) ? (u | 0x80000000u) : ~u;
}
__device__ __forceinline__ float funkey(unsigned u) {
    return __int_as_float((u & 0x80000000u) ? (int)(u ^ 0x80000000u) : (int)(~u));
}

// Bracket-safeguarded Newton for sum(clip(vr - tau, 0, MAXW)) == 1.
// Warp-replicated and deterministic: every warp computes the identical tau with
// NO cross-warp communication (no SMEM, no barriers). s(tau) is piecewise linear,
// slope -m where m = #active; Newton is exact within a linear piece, so a warm
// start typically converges in 1-2 evals.
__device__ __forceinline__ float solve_tau(const float (&vr)[8], float tau0, int warm) {
    float mn = fminf(fminf(fminf(vr[0], vr[1]), fminf(vr[2], vr[3])),
                     fminf(fminf(vr[4], vr[5]), fminf(vr[6], vr[7])));
    float mx = fmaxf(fmaxf(fmaxf(vr[0], vr[1]), fmaxf(vr[2], vr[3])),
                     fmaxf(fmaxf(vr[4], vr[5]), fmaxf(vr[6], vr[7])));
    mn = funkey(__reduce_min_sync(0xffffffffu, fkey(mn)));
    mx = funkey(__reduce_max_sync(0xffffffffu, fkey(mx)));
    float lo = mn - MAXW, hi = mx;           // s(lo)=25.6>=1, s(hi)=0<=1: valid bracket
    float tau = warm ? fminf(fmaxf(tau0, lo), hi) : 0.5f * (lo + hi);

    for (int i = 0; i < 14; i++) {
        float s = 0.f; int m = 0;
#pragma unroll
        for (int k = 0; k < 8; k++) {
            const float d = vr[k] - tau;
            s += fminf(fmaxf(d, 0.f), MAXW);
            m += (d > 0.f) && (d < MAXW);
        }
        int si = __float2int_rn(s * FPSCALE);
        si = __reduce_add_sync(0xffffffffu, si);
        m  = __reduce_add_sync(0xffffffffu, m);
        const int err = si - FPONE;
        if (err >= -1 && err <= 1) return tau;            // |s-1| <= 6e-8: done
        if (err > 0) lo = tau; else hi = tau;
        if (hi - lo < 1e-9f) break;
        float t = (m > 0) ? fmaf((float)err, (1.0f / FPSCALE) / (float)m, tau)
                          : 0.5f * (lo + hi);
        tau = (t > lo && t < hi) ? t : 0.5f * (lo + hi);  // safeguard
    }
    return 0.5f * (lo + hi);
}

// Mat-vec: y = sigma * x. Rows 0..127 from SMEM, rows 128..255 from register file rf[64].
// Thread t: row_lo = t>>2, row_hi = 128 + (t>>2), chunk = t&3, cols staggered per chunk.
__device__ __forceinline__ void matvec256(const float* __restrict__ sm,
                                          const float (&rf)[64],
                                          int sbase, int xbase, int chunk,
                                          float& Y0, float& Y1) {
    float a0 = 0.f, b0 = 0.f, a1 = 0.f, b1 = 0.f;
#pragma unroll
    for (int i = 0; i < 16; i++) {
        const int cm = 4 * ((i + 2 * chunk) & 15);
        const float4 xv = *reinterpret_cast<const float4*>(&sm[xbase + cm]);
        const float4 sv = *reinterpret_cast<const float4*>(&sm[sbase + cm]);
        if (i & 1) {
            b0 = fmaf(sv.x, xv.x, b0); b0 = fmaf(sv.y, xv.y, b0);
            b0 = fmaf(sv.z, xv.z, b0); b0 = fmaf(sv.w, xv.w, b0);
            b1 = fmaf(rf[4 * i + 0], xv.x, b1); b1 = fmaf(rf[4 * i + 1], xv.y, b1);
            b1 = fmaf(rf[4 * i + 2], xv.z, b1); b1 = fmaf(rf[4 * i + 3], xv.w, b1);
        } else {
            a0 = fmaf(sv.x, xv.x, a0); a0 = fmaf(sv.y, xv.y, a0);
            a0 = fmaf(sv.z, xv.z, a0); a0 = fmaf(sv.w, xv.w, a0);
            a1 = fmaf(rf[4 * i + 0], xv.x, a1); a1 = fmaf(rf[4 * i + 1], xv.y, a1);
            a1 = fmaf(rf[4 * i + 2], xv.z, a1); a1 = fmaf(rf[4 * i + 3], xv.w, a1);
        }
    }
    a0 += b0; a1 += b1;
    a0 += __shfl_xor_sync(0xffffffffu, a0, 1);
    a1 += __shfl_xor_sync(0xffffffffu, a1, 1);
    a0 += __shfl_xor_sync(0xffffffffu, a0, 2);
    a1 += __shfl_xor_sync(0xffffffffu, a1, 2);
    Y0 = a0; Y1 = a1;
}

__global__ __launch_bounds__(512, 1)
void drb_kernel(const float* __restrict__ sigma,
                const float* __restrict__ beta,
                const float* __restrict__ wprev,
                const float* __restrict__ ll1,
                const float* __restrict__ ll2,
                float* __restrict__ out) {
    extern __shared__ float sm[];
    int* const smi = reinterpret_cast<int*>(sm);
    const int tid    = threadIdx.x;
    const int b      = blockIdx.x;
    const int chunk  = tid & 3;
    const int col0   = chunk * 64;
    const int row_lo = tid >> 2;          // 0..127
    const int row_hi = 128 + row_lo;      // 128..255
    const int lane   = tid & 31;
    const int wid    = tid >> 5;          // 0..15
    const int sbase  = row_lo * RP + col0;
    const int xbase  = XS_OFF + col0;

    const float lam1 = expf(ll1[0]);
    const float lam2 = expf(ll2[0]);

    const size_t gb = (size_t)b * PP * PP;

    // ---- register-resident half of sigma (rows 128..255), staggered col order ----
    float rf[64];
    {
        const float* grow = sigma + gb + (size_t)row_hi * PP + col0;
#pragma unroll
        for (int i = 0; i < 16; i++) {
            const int cm = 4 * ((i + 2 * chunk) & 15);
            const float4 v = *reinterpret_cast<const float4*>(&grow[cm]);
            rf[4 * i + 0] = v.x; rf[4 * i + 1] = v.y;
            rf[4 * i + 2] = v.z; rf[4 * i + 3] = v.w;
        }
    }

    // ---- SMEM-resident half of sigma (rows 0..127), padded rows ----
    for (int idx = tid; idx < SROWS * 64; idx += 512) {
        const int r = idx >> 6, c4 = idx & 63;
        const float4 v = *reinterpret_cast<const float4*>(&sigma[gb + (size_t)r * PP + c4 * 4]);
        *reinterpret_cast<float4*>(&sm[r * RP + c4 * 4]) = v;
    }

    const float beta0 = beta[b * PP + row_lo];
    const float beta1 = beta[b * PP + row_hi];
    const float wp0   = wprev[b * PP + row_lo];
    const float wp1   = wprev[b * PP + row_hi];

    // ---- power iteration: v0 = 1/sqrt(P) ----
    if (tid < 256) sm[XS_OFF + tid] = 0.0625f;
    __syncthreads();

    for (int it = 0; it < NPOW; it++) {
        float u0, u1;
        matvec256(sm, rf, sbase, xbase, chunk, u0, u1);
        if (chunk == 0) { sm[VS_OFF + row_lo] = u0; sm[VS_OFF + row_hi] = u1; }
        __syncthreads();
        float ns = 0.f;
#pragma unroll
        for (int k = 0; k < 8; k++) {
            const float t = sm[VS_OFF + lane + 32 * k];
            ns = fmaf(t, t, ns);
        }
        ns = bfly_add(ns);
        const float inv = 1.0f / (sqrtf(ns) + EPSI);
        if (tid < 256) sm[XS_OFF + tid] = sm[VS_OFF + tid] * inv;
        __syncthreads();
    }

    // ---- lmax = v' S v, step = 1/(2 lmax + 2 lam2 + 1e-6) ----
    float step;
    {
        float u0, u1;
        matvec256(sm, rf, sbase, xbase, chunk, u0, u1);
        if (chunk == 0) {
            sm[VS_OFF + row_lo] = u0 * sm[XS_OFF + row_lo];
            sm[VS_OFF + row_hi] = u1 * sm[XS_OFF + row_hi];
        }
        __syncthreads();
        float lm = 0.f;
#pragma unroll
        for (int k = 0; k < 8; k++) lm += sm[VS_OFF + lane + 32 * k];
        lm = bfly_add(lm);
        step = 1.0f / (2.0f * lm + 2.0f * lam2 + 1e-6f);
        if (tid < 256) sm[XS_OFF + tid] = 1.0f / 256.0f;   // w0 = 1/P
        if (tid < 2)   smi[FL_OFF + tid] = 0;              // convergence flags
        __syncthreads();
    }

    float tau_p = 0.f;
    int   have_warm = 0;
    float pw0 = 1.0f / 256.0f, pw1 = 1.0f / 256.0f;        // prev w for early-exit check
    const int kk   = wid >> 1;                              // vr reg this warp writes back
    const int wsel = ((lane >> 4) == (wid & 1));

    // ---- projected gradient descent ----
    for (int it = 0; it < NPGD; it++) {
        float y0, y1;
        matvec256(sm, rf, sbase, xbase, chunk, y0, y1);
        if (chunk == 0) {
            const float w0 = sm[XS_OFF + row_lo];
            const float w1 = sm[XS_OFF + row_hi];
            // early-exit bookkeeping: has w moved during iteration it-1?
            const float dmax = fmaxf(fabsf(w0 - pw0), fabsf(w1 - pw1));
            pw0 = w0; pw1 = w1;
            if (dmax > 1e-7f) smi[FL_OFF + (it & 1)] = 1;
            const float g0 = fmaf(2.0f, y0, -beta0) + lam1 + 2.0f * lam2 * (w0 - wp0);
            const float g1 = fmaf(2.0f, y1, -beta1) + lam1 + 2.0f * lam2 * (w1 - wp1);
            sm[VS_OFF + row_lo] = fmaf(-step, g0, w0);
            sm[VS_OFF + row_hi] = fmaf(-step, g1, w1);
        }
        __syncthreads();

        // ---- projection: warp-replicated safeguarded Newton (no barriers) ----
        float vr[8];
#pragma unroll
        for (int k = 0; k < 8; k++) vr[k] = sm[VS_OFF + lane + 32 * k];

        const float tau = solve_tau(vr, tau_p, have_warm);
        tau_p = tau;
        have_warm = 1;

        // distributed write-back: warp w writes its 16 indices
        if (wsel) sm[XS_OFF + lane + 32 * kk] = fminf(fmaxf(vr[kk] - tau, 0.f), MAXW);
        if (tid == 0) smi[FL_OFF + ((it + 1) & 1)] = 0;   // reset next-iter flag
        __syncthreads();

        // The flag measures the delta taken during iteration it-1; at it==0 there is
        // no previous step (dmax==0 trivially) -> never exit on the first iteration.
        if (it > 0 && smi[FL_OFF + (it & 1)] == 0) break; // fixpoint reached: done
    }

    // ---- post: renormalize w / (sum + eps) ----
    float s = 0.f;
#pragma unroll
    for (int k = 0; k < 8; k++) s += sm[XS_OFF + lane + 32 * k];
    s = bfly_add(s);
    const float inv = 1.0f / (s + EPSI);
    if (tid < 256) out[(size_t)b * PP + tid] = sm[XS_OFF + tid] * inv;
}

extern "C" void kernel_launch(void* const* d_in, const int* in_sizes, int n_in,
                              void* d_out, int out_size) {
    const float* sigma = (const float*)d_in[0];
    const float* beta  = (const float*)d_in[1];
    const float* wprev = (const float*)d_in[2];
    const float* ll1   = (const float*)d_in[3];
    const float* ll2   = (const float*)d_in[4];
    float* out = (float*)d_out;

    cudaFuncSetAttribute(drb_kernel, cudaFuncAttributeMaxDynamicSharedMemorySize, SMEM_BYTES);
    drb_kernel<<<BB, 512, SMEM_BYTES>>>(sigma, beta, wprev, ll1, ll2, out);
}